// round 1
// baseline (speedup 1.0000x reference)
#include <cuda_runtime.h>
#include <cuda_bf16.h>
#include <math_constants.h>

#define NSEQ    2048
#define DHEAD   128
#define BR      64
#define BC      64
#define KSTR    132   // smem row stride (floats) for Q/K/V tiles (pad to kill conflicts)
#define PSTR    68    // smem row stride for P tile
#define NWARP   4
#define NTHR    128
#define LOG2E   1.4426950408889634f

// dynamic smem: Q(64x132) reused as P(64x68), K(64x132), V(64x132) -> all u32 (tf32 bits)
#define SMEM_BYTES (3 * BR * KSTR * 4)

__device__ __forceinline__ unsigned f2tf(float x) {
    unsigned y;
    asm("cvt.rna.tf32.f32 %0, %1;" : "=r"(y) : "f"(x));
    return y;
}

__device__ __forceinline__ void mma_tf32(float* d, const unsigned* a, const unsigned* b) {
    asm volatile(
        "mma.sync.aligned.m16n8k8.row.col.f32.tf32.tf32.f32 "
        "{%0,%1,%2,%3}, {%4,%5,%6,%7}, {%8,%9}, {%0,%1,%2,%3};\n"
        : "+f"(d[0]), "+f"(d[1]), "+f"(d[2]), "+f"(d[3])
        : "r"(a[0]), "r"(a[1]), "r"(a[2]), "r"(a[3]),
          "r"(b[0]), "r"(b[1]));
}

extern __shared__ unsigned smem_u[];

__global__ __launch_bounds__(NTHR, 1)
void fattn_tf32_kernel(const float* __restrict__ Q,
                       const float* __restrict__ K,
                       const float* __restrict__ V,
                       float* __restrict__ O)
{
    const int qi   = blockIdx.x;          // q tile index (0..31)
    const int b    = blockIdx.y;          // batch
    const int t    = threadIdx.x;
    const int lane = t & 31;
    const int warp = t >> 5;
    const int g    = lane >> 2;           // group id (row within mma tile)
    const int tig  = lane & 3;            // thread in group

    unsigned* Qs = smem_u;                     // 64 x KSTR (later reused as P: 64 x PSTR)
    unsigned* Ks = smem_u + BR * KSTR;         // 64 x KSTR
    unsigned* Vs = Ks + BC * KSTR;             // 64 x KSTR
    unsigned* Ps = smem_u;                     // alias of Qs

    const float scale = 0.08838834764831845f;  // 1/sqrt(128)
    const int q0 = qi * BR;
    const float* qbase = Q + ((size_t)b * NSEQ + q0) * DHEAD;

    // ---- load Q tile (pre-scaled, tf32) ----
    #pragma unroll
    for (int i = 0; i < 16; i++) {
        int e = (i * NTHR + t) * 4;     // element index in 64x128 tile
        int r = e >> 7, c = e & 127;
        float4 f = *(const float4*)(qbase + r * DHEAD + c);
        Qs[r * KSTR + c + 0] = f2tf(f.x * scale);
        Qs[r * KSTR + c + 1] = f2tf(f.y * scale);
        Qs[r * KSTR + c + 2] = f2tf(f.z * scale);
        Qs[r * KSTR + c + 3] = f2tf(f.w * scale);
    }
    __syncthreads();

    // ---- hoist Q A-fragments into registers (K loop reuses them every step) ----
    const int rl0 = warp * 16 + g;     // local row (first of the pair)
    unsigned qf[16][4];
    #pragma unroll
    for (int kk = 0; kk < 16; kk++) {
        qf[kk][0] = Qs[ rl0      * KSTR + kk * 8 + tig];
        qf[kk][1] = Qs[(rl0 + 8) * KSTR + kk * 8 + tig];
        qf[kk][2] = Qs[ rl0      * KSTR + kk * 8 + tig + 4];
        qf[kk][3] = Qs[(rl0 + 8) * KSTR + kk * 8 + tig + 4];
    }
    __syncthreads();   // everyone done reading Q smem; it becomes the P buffer

    float o[16][4];
    #pragma unroll
    for (int j = 0; j < 16; j++) {
        o[j][0] = 0.f; o[j][1] = 0.f; o[j][2] = 0.f; o[j][3] = 0.f;
    }
    float m0 = -CUDART_INF_F, m1 = -CUDART_INF_F;
    float l0 = 0.f, l1 = 0.f;

    for (int kt = 0; kt <= qi; kt++) {
        // ---- load K and V tiles (tf32) ----
        const float* kb = K + ((size_t)b * NSEQ + kt * BC) * DHEAD;
        const float* vb = V + ((size_t)b * NSEQ + kt * BC) * DHEAD;
        #pragma unroll
        for (int i = 0; i < 16; i++) {
            int e = (i * NTHR + t) * 4;
            int r = e >> 7, c = e & 127;
            float4 fk = *(const float4*)(kb + r * DHEAD + c);
            Ks[r * KSTR + c + 0] = f2tf(fk.x);
            Ks[r * KSTR + c + 1] = f2tf(fk.y);
            Ks[r * KSTR + c + 2] = f2tf(fk.z);
            Ks[r * KSTR + c + 3] = f2tf(fk.w);
            float4 fv = *(const float4*)(vb + r * DHEAD + c);
            Vs[r * KSTR + c + 0] = f2tf(fv.x);
            Vs[r * KSTR + c + 1] = f2tf(fv.y);
            Vs[r * KSTR + c + 2] = f2tf(fv.z);
            Vs[r * KSTR + c + 3] = f2tf(fv.w);
        }
        __syncthreads();

        // ---- S = Q * K^T  (16 rows x 64 cols per warp) ----
        float s[8][4];
        #pragma unroll
        for (int j = 0; j < 8; j++) {
            s[j][0] = 0.f; s[j][1] = 0.f; s[j][2] = 0.f; s[j][3] = 0.f;
        }
        #pragma unroll
        for (int kk = 0; kk < 16; kk++) {
            #pragma unroll
            for (int jn = 0; jn < 8; jn++) {
                unsigned bf[2];
                bf[0] = Ks[(jn * 8 + g) * KSTR + kk * 8 + tig];
                bf[1] = Ks[(jn * 8 + g) * KSTR + kk * 8 + tig + 4];
                mma_tf32(s[jn], qf[kk], bf);
            }
        }

        // ---- causal mask (diagonal tile only) ----
        if (kt == qi) {
            #pragma unroll
            for (int jn = 0; jn < 8; jn++) {
                int cb = jn * 8 + 2 * tig;   // local col (tile-local == row-local compare)
                if (cb     > rl0)     s[jn][0] = -CUDART_INF_F;
                if (cb + 1 > rl0)     s[jn][1] = -CUDART_INF_F;
                if (cb     > rl0 + 8) s[jn][2] = -CUDART_INF_F;
                if (cb + 1 > rl0 + 8) s[jn][3] = -CUDART_INF_F;
            }
        }

        // ---- online softmax ----
        float mx0 = -CUDART_INF_F, mx1 = -CUDART_INF_F;
        #pragma unroll
        for (int jn = 0; jn < 8; jn++) {
            mx0 = fmaxf(mx0, fmaxf(s[jn][0], s[jn][1]));
            mx1 = fmaxf(mx1, fmaxf(s[jn][2], s[jn][3]));
        }
        mx0 = fmaxf(mx0, __shfl_xor_sync(0xffffffffu, mx0, 1));
        mx0 = fmaxf(mx0, __shfl_xor_sync(0xffffffffu, mx0, 2));
        mx1 = fmaxf(mx1, __shfl_xor_sync(0xffffffffu, mx1, 1));
        mx1 = fmaxf(mx1, __shfl_xor_sync(0xffffffffu, mx1, 2));

        float mn0 = fmaxf(m0, mx0);
        float mn1 = fmaxf(m1, mx1);
        float a0 = exp2f((m0 - mn0) * LOG2E);
        float a1 = exp2f((m1 - mn1) * LOG2E);

        float rs0 = 0.f, rs1 = 0.f;
        #pragma unroll
        for (int jn = 0; jn < 8; jn++) {
            s[jn][0] = exp2f((s[jn][0] - mn0) * LOG2E);
            s[jn][1] = exp2f((s[jn][1] - mn0) * LOG2E);
            s[jn][2] = exp2f((s[jn][2] - mn1) * LOG2E);
            s[jn][3] = exp2f((s[jn][3] - mn1) * LOG2E);
            rs0 += s[jn][0] + s[jn][1];
            rs1 += s[jn][2] + s[jn][3];
        }
        rs0 += __shfl_xor_sync(0xffffffffu, rs0, 1);
        rs0 += __shfl_xor_sync(0xffffffffu, rs0, 2);
        rs1 += __shfl_xor_sync(0xffffffffu, rs1, 1);
        rs1 += __shfl_xor_sync(0xffffffffu, rs1, 2);

        l0 = l0 * a0 + rs0;
        l1 = l1 * a1 + rs1;
        m0 = mn0; m1 = mn1;

        #pragma unroll
        for (int j = 0; j < 16; j++) {
            o[j][0] *= a0; o[j][1] *= a0;
            o[j][2] *= a1; o[j][3] *= a1;
        }

        // ---- stage P (warp-private rows; tf32) ----
        #pragma unroll
        for (int jn = 0; jn < 8; jn++) {
            int c = jn * 8 + 2 * tig;
            Ps[ rl0      * PSTR + c    ] = f2tf(s[jn][0]);
            Ps[ rl0      * PSTR + c + 1] = f2tf(s[jn][1]);
            Ps[(rl0 + 8) * PSTR + c    ] = f2tf(s[jn][2]);
            Ps[(rl0 + 8) * PSTR + c + 1] = f2tf(s[jn][3]);
        }
        __syncwarp();

        // ---- O += P * V ----
        #pragma unroll
        for (int kk = 0; kk < 8; kk++) {
            unsigned af[4];
            af[0] = Ps[ rl0      * PSTR + kk * 8 + tig];
            af[1] = Ps[(rl0 + 8) * PSTR + kk * 8 + tig];
            af[2] = Ps[ rl0      * PSTR + kk * 8 + tig + 4];
            af[3] = Ps[(rl0 + 8) * PSTR + kk * 8 + tig + 4];
            #pragma unroll
            for (int jn = 0; jn < 16; jn++) {
                unsigned bf[2];
                bf[0] = Vs[(kk * 8 + tig)     * KSTR + jn * 8 + g];
                bf[1] = Vs[(kk * 8 + tig + 4) * KSTR + jn * 8 + g];
                mma_tf32(o[jn], af, bf);
            }
        }
        __syncthreads();   // protect K/V smem for next iteration
    }

    // ---- epilogue ----
    float inv0 = 1.f / l0;
    float inv1 = 1.f / l1;
    float* ob = O + ((size_t)b * NSEQ + q0) * DHEAD;
    #pragma unroll
    for (int jn = 0; jn < 16; jn++) {
        int c = jn * 8 + 2 * tig;
        float2 w0 = make_float2(o[jn][0] * inv0, o[jn][1] * inv0);
        float2 w1 = make_float2(o[jn][2] * inv1, o[jn][3] * inv1);
        *(float2*)(ob + (size_t)(rl0    ) * DHEAD + c) = w0;
        *(float2*)(ob + (size_t)(rl0 + 8) * DHEAD + c) = w1;
    }
}

extern "C" void kernel_launch(void* const* d_in, const int* in_sizes, int n_in,
                              void* d_out, int out_size)
{
    const float* q = (const float*)d_in[0];
    const float* k = (const float*)d_in[1];
    const float* v = (const float*)d_in[2];
    float* out = (float*)d_out;
    (void)in_sizes; (void)n_in; (void)out_size;

    cudaFuncSetAttribute(fattn_tf32_kernel,
                         cudaFuncAttributeMaxDynamicSharedMemorySize, SMEM_BYTES);

    dim3 grid(NSEQ / BR, 16);   // 32 q-tiles x 16 batches
    fattn_tf32_kernel<<<grid, NTHR, SMEM_BYTES>>>(q, k, v, out);
}